// round 2
// baseline (speedup 1.0000x reference)
#include <cuda_runtime.h>
#include <cuda_bf16.h>

#define NUM_SEG 32
#define C 256
#define C4 64   // float4 per row

// Scratch (allocation-free rule: __device__ globals)
__device__ float  g_sum[NUM_SEG * C];
__device__ float4 g_y4[NUM_SEG * C4];   // gates, float4-aligned

// ---------------------------------------------------------------------------
// Kernel 0: zero the accumulator (graph replays -> must re-zero every launch)
// ---------------------------------------------------------------------------
__global__ void se_zero_kernel() {
    int i = blockIdx.x * blockDim.x + threadIdx.x;
    if (i < NUM_SEG * C) g_sum[i] = 0.0f;
}

// ---------------------------------------------------------------------------
// Kernel 1: segment sum. Block owns ROWS_PER_BLOCK contiguous rows. Since
// batch_idx is sorted, almost every block lives entirely in ONE segment:
// fast path = branch-free unrolled accumulate (no idx loads in the hot loop,
// independent accumulators for memory-level parallelism), single atomic
// flush. Rare boundary blocks take the per-row fallback.
// 256 threads = 64 float4 channel lanes x 4 subrows.
// ---------------------------------------------------------------------------
#define ROWS_PER_BLOCK 512

__device__ __forceinline__ void flush_acc(int seg, int c4, float4 a) {
    float* dst = &g_sum[seg * C + c4 * 4];
    atomicAdd(dst + 0, a.x);
    atomicAdd(dst + 1, a.y);
    atomicAdd(dst + 2, a.z);
    atomicAdd(dst + 3, a.w);
}

__global__ void se_reduce_kernel(const float4* __restrict__ feats,
                                 const int*    __restrict__ idx,
                                 int N) {
    const int c4  = threadIdx.x & 63;   // channel float4 lane
    const int sub = threadIdx.x >> 6;   // 0..3
    long base = (long)blockIdx.x * ROWS_PER_BLOCK;
    long end  = base + ROWS_PER_BLOCK;
    if (end > N) end = N;

    const int s_first = __ldg(&idx[base]);
    const int s_last  = __ldg(&idx[end - 1]);

    if (s_first == s_last) {
        // ---- fast path: whole block in one segment ----
        float4 a0 = make_float4(0.f, 0.f, 0.f, 0.f);
        float4 a1 = make_float4(0.f, 0.f, 0.f, 0.f);
        const float4* p = feats + (base + sub) * C4 + c4;
        long r = base + sub;
        // 4 independent loads per iteration (rows r, r+4, r+8, r+12)
        for (; r + 12 < end; r += 16) {
            float4 v0 = p[0 * C4 * 4];
            float4 v1 = p[1 * C4 * 4];
            float4 v2 = p[2 * C4 * 4];
            float4 v3 = p[3 * C4 * 4];
            a0.x += v0.x; a0.y += v0.y; a0.z += v0.z; a0.w += v0.w;
            a1.x += v1.x; a1.y += v1.y; a1.z += v1.z; a1.w += v1.w;
            a0.x += v2.x; a0.y += v2.y; a0.z += v2.z; a0.w += v2.w;
            a1.x += v3.x; a1.y += v3.y; a1.z += v3.z; a1.w += v3.w;
            p += 16 * C4;
        }
        for (; r < end; r += 4) {
            float4 v = p[0];
            a0.x += v.x; a0.y += v.y; a0.z += v.z; a0.w += v.w;
            p += 4 * C4;
        }
        a0.x += a1.x; a0.y += a1.y; a0.z += a1.z; a0.w += a1.w;
        flush_acc(s_first, c4, a0);
    } else {
        // ---- fallback: block straddles a segment boundary ----
        float4 acc = make_float4(0.f, 0.f, 0.f, 0.f);
        int cur = -1;
        for (long r = base + sub; r < end; r += 4) {
            int s = __ldg(&idx[r]);
            float4 v = feats[r * C4 + c4];
            if (s != cur) {
                if (cur >= 0) flush_acc(cur, c4, acc);
                cur = s;
                acc = v;
            } else {
                acc.x += v.x; acc.y += v.y; acc.z += v.z; acc.w += v.w;
            }
        }
        if (cur >= 0) flush_acc(cur, c4, acc);
    }
}

// ---------------------------------------------------------------------------
// Kernel 2: counts (binary search on sorted idx) + mean + MLP + sigmoid.
// Single block, 256 threads. ~0.5 MFLOP — negligible.
// ---------------------------------------------------------------------------
__global__ void se_mlp_kernel(const int*   __restrict__ idx, int N,
                              const float* __restrict__ W1,
                              const float* __restrict__ b1,
                              const float* __restrict__ W2,
                              const float* __restrict__ b2) {
    __shared__ float s_pooled[NUM_SEG * C];   // 32 KB
    __shared__ float s_h[NUM_SEG * 16];
    __shared__ int   s_lb[NUM_SEG + 1];

    const int t = threadIdx.x;

    // lower_bound(idx, s) for s = 0..32
    if (t <= NUM_SEG) {
        int lo = 0, hi = N;
        while (lo < hi) {
            int mid = (lo + hi) >> 1;
            if (idx[mid] < t) lo = mid + 1; else hi = mid;
        }
        s_lb[t] = lo;
    }
    __syncthreads();

    // pooled = sum / max(count, 1)
    for (int i = t; i < NUM_SEG * C; i += 256) {
        int s = i >> 8;   // / C
        float cnt = (float)(s_lb[s + 1] - s_lb[s]);
        s_pooled[i] = g_sum[i] / fmaxf(cnt, 1.0f);
    }
    __syncthreads();

    // h = relu(pooled @ W1 + b1)   [32 x 16]
    for (int o = t; o < NUM_SEG * 16; o += 256) {
        int s = o >> 4;
        int j = o & 15;
        float accv = b1[j];
        const float* p = &s_pooled[s * C];
        #pragma unroll 8
        for (int k = 0; k < C; k++) accv += p[k] * W1[k * 16 + j];
        s_h[o] = fmaxf(accv, 0.0f);
    }
    __syncthreads();

    // y = sigmoid(h @ W2 + b2)   [32 x 256]
    float* y = (float*)g_y4;
    for (int o = t; o < NUM_SEG * C; o += 256) {
        int s = o >> 8;
        int j = o & 255;
        float accv = b2[j];
        const float* hh = &s_h[s * 16];
        #pragma unroll
        for (int k = 0; k < 16; k++) accv += hh[k] * W2[k * C + j];
        y[o] = 1.0f / (1.0f + __expf(-accv));
    }
}

// ---------------------------------------------------------------------------
// Kernel 3: out = feats * y[batch_idx].  Flat float4 grid-stride.
// idx (4MB) and gates (32KB) stay L1/L2 resident.  84.6% DRAM already.
// ---------------------------------------------------------------------------
__global__ void se_scale_kernel(const float4* __restrict__ feats,
                                const int*    __restrict__ idx,
                                float4*       __restrict__ out,
                                long total4) {
    long stride = (long)gridDim.x * blockDim.x;
    for (long i = (long)blockIdx.x * blockDim.x + threadIdx.x;
         i < total4; i += stride) {
        int row = (int)(i >> 6);
        int c4  = (int)(i & 63);
        int s   = __ldg(&idx[row]);
        float4 v = feats[i];
        float4 g = g_y4[s * C4 + c4];
        float4 o;
        o.x = v.x * g.x; o.y = v.y * g.y; o.z = v.z * g.z; o.w = v.w * g.w;
        out[i] = o;
    }
}

// ---------------------------------------------------------------------------
extern "C" void kernel_launch(void* const* d_in, const int* in_sizes, int n_in,
                              void* d_out, int out_size) {
    const float* feats = (const float*)d_in[0];
    const int*   idx   = (const int*)  d_in[1];
    const float* W1    = (const float*)d_in[2];
    const float* b1    = (const float*)d_in[3];
    const float* W2    = (const float*)d_in[4];
    const float* b2    = (const float*)d_in[5];

    const int N = in_sizes[1];               // number of points
    const long total4 = (long)N * C4;

    se_zero_kernel<<<(NUM_SEG * C + 255) / 256, 256>>>();

    int rblocks = (N + ROWS_PER_BLOCK - 1) / ROWS_PER_BLOCK;
    se_reduce_kernel<<<rblocks, 256>>>((const float4*)feats, idx, N);

    se_mlp_kernel<<<1, 256>>>(idx, N, W1, b1, W2, b2);

    se_scale_kernel<<<2368, 256>>>((const float4*)feats, idx,
                                   (float4*)d_out, total4);
}

// round 3
// speedup vs baseline: 1.1402x; 1.1402x over previous
#include <cuda_runtime.h>
#include <cuda_bf16.h>

#define NUM_SEG 32
#define C 256
#define C4 64   // float4 per row

// Scratch (allocation-free rule: __device__ globals)
__device__ float  g_sum[NUM_SEG * C];
__device__ float4 g_y4[NUM_SEG * C4];   // gates, float4-aligned

// ---------------------------------------------------------------------------
// Kernel 0: zero the accumulator (graph replays -> must re-zero every launch)
// ---------------------------------------------------------------------------
__global__ void se_zero_kernel() {
    int i = blockIdx.x * blockDim.x + threadIdx.x;
    if (i < NUM_SEG * C) g_sum[i] = 0.0f;
}

// ---------------------------------------------------------------------------
// Kernel 1: segment sum, single-wave even partition.
// Grid = 152 SMs * 6 CTAs (launch_bounds guarantees 6 resident/SM), each
// block owns a contiguous equal slice of rows -> zero wave quantization and
// zero tail. Inside, walk in 128-row chunks: if idx[chunk_end-1] == cur
// (sorted => whole chunk is one segment), take the branch-free unrolled
// path; else per-row fallback. Atomic flush only on segment change.
// 256 threads = 64 float4 channel lanes x 4 subrows.
// ---------------------------------------------------------------------------
#define RED_BLOCKS (152 * 6)
#define CHUNK 128

__device__ __forceinline__ void flush_acc(int seg, int c4, float4 a0, float4 a1) {
    float* dst = &g_sum[seg * C + c4 * 4];
    atomicAdd(dst + 0, a0.x + a1.x);
    atomicAdd(dst + 1, a0.y + a1.y);
    atomicAdd(dst + 2, a0.z + a1.z);
    atomicAdd(dst + 3, a0.w + a1.w);
}

__global__ void __launch_bounds__(256, 6)
se_reduce_kernel(const float4* __restrict__ feats,
                 const int*    __restrict__ idx,
                 int N) {
    const int c4  = threadIdx.x & 63;   // channel float4 lane
    const int sub = threadIdx.x >> 6;   // 0..3

    // even contiguous partition of rows across blocks
    long r0 = (long)blockIdx.x * N / gridDim.x;
    long r1 = (long)(blockIdx.x + 1) * N / gridDim.x;
    if (r0 >= r1) return;

    float4 a0 = make_float4(0.f, 0.f, 0.f, 0.f);
    float4 a1 = make_float4(0.f, 0.f, 0.f, 0.f);
    int cur = __ldg(&idx[r0]);

    long cs = r0;
    while (cs < r1) {
        long ce = cs + CHUNK;
        if (ce > r1) ce = r1;
        int s_last = __ldg(&idx[ce - 1]);

        if (s_last == cur) {
            // fast path: whole chunk in this thread's current segment
            const float4* p = feats + (cs + sub) * C4 + c4;
            long r = cs + sub;
            for (; r + 12 < ce; r += 16) {
                float4 v0 = p[0 * 4 * C4];
                float4 v1 = p[1 * 4 * C4];
                float4 v2 = p[2 * 4 * C4];
                float4 v3 = p[3 * 4 * C4];
                a0.x += v0.x; a0.y += v0.y; a0.z += v0.z; a0.w += v0.w;
                a1.x += v1.x; a1.y += v1.y; a1.z += v1.z; a1.w += v1.w;
                a0.x += v2.x; a0.y += v2.y; a0.z += v2.z; a0.w += v2.w;
                a1.x += v3.x; a1.y += v3.y; a1.z += v3.z; a1.w += v3.w;
                p += 16 * C4;
            }
            for (; r < ce; r += 4) {
                float4 v = p[0];
                a0.x += v.x; a0.y += v.y; a0.z += v.z; a0.w += v.w;
                p += 4 * C4;
            }
        } else {
            // boundary chunk: per-row segment tracking
            for (long r = cs + sub; r < ce; r += 4) {
                int s = __ldg(&idx[r]);
                float4 v = feats[r * C4 + c4];
                if (s != cur) {
                    flush_acc(cur, c4, a0, a1);
                    a0 = v;
                    a1 = make_float4(0.f, 0.f, 0.f, 0.f);
                    cur = s;
                } else {
                    a0.x += v.x; a0.y += v.y; a0.z += v.z; a0.w += v.w;
                }
            }
        }
        cs = ce;
    }
    flush_acc(cur, c4, a0, a1);
}

// ---------------------------------------------------------------------------
// Kernel 2: one block per segment. Binary-search bounds (sorted idx), mean,
// 256->16 GEMM (16-thread groups + shuffle reduce), ReLU, 16->256 GEMM,
// sigmoid. 32 blocks x 256 threads.
// ---------------------------------------------------------------------------
__global__ void se_mlp_kernel(const int*   __restrict__ idx, int N,
                              const float* __restrict__ W1,
                              const float* __restrict__ b1,
                              const float* __restrict__ W2,
                              const float* __restrict__ b2) {
    const int s = blockIdx.x;
    const int t = threadIdx.x;
    __shared__ float sp[C];
    __shared__ float sh[16];
    __shared__ int   lb[2];

    // lower_bound(idx, s) and lower_bound(idx, s+1)
    if (t < 2) {
        int target = s + t;
        int lo = 0, hi = N;
        while (lo < hi) {
            int mid = (lo + hi) >> 1;
            if (__ldg(&idx[mid]) < target) lo = mid + 1; else hi = mid;
        }
        lb[t] = lo;
    }
    __syncthreads();

    float inv_cnt = 1.0f / fmaxf((float)(lb[1] - lb[0]), 1.0f);
    sp[t] = g_sum[s * C + t] * inv_cnt;
    __syncthreads();

    // h[g] = relu(dot(sp, W1[:,g]) + b1[g]); 16 threads per output g
    {
        int g = t >> 4;       // output 0..15
        int l = t & 15;       // lane within group
        float acc = 0.0f;
        #pragma unroll
        for (int k = l; k < C; k += 16) acc += sp[k] * W1[k * 16 + g];
        #pragma unroll
        for (int off = 8; off; off >>= 1)
            acc += __shfl_down_sync(0xffffffffu, acc, off, 16);
        if (l == 0) sh[g] = fmaxf(acc + b1[g], 0.0f);
    }
    __syncthreads();

    // y[t] = sigmoid(dot(sh, W2[:,t]) + b2[t])
    float acc = b2[t];
    #pragma unroll
    for (int k = 0; k < 16; k++) acc += sh[k] * W2[k * C + t];
    ((float*)g_y4)[s * C + t] = 1.0f / (1.0f + __expf(-acc));
}

// ---------------------------------------------------------------------------
// Kernel 3: out = feats * y[batch_idx].  Flat float4 grid-stride.
// Already at 84.6% DRAM (6.7 TB/s) — unchanged.
// ---------------------------------------------------------------------------
__global__ void se_scale_kernel(const float4* __restrict__ feats,
                                const int*    __restrict__ idx,
                                float4*       __restrict__ out,
                                long total4) {
    long stride = (long)gridDim.x * blockDim.x;
    for (long i = (long)blockIdx.x * blockDim.x + threadIdx.x;
         i < total4; i += stride) {
        int row = (int)(i >> 6);
        int c4  = (int)(i & 63);
        int s   = __ldg(&idx[row]);
        float4 v = feats[i];
        float4 g = g_y4[s * C4 + c4];
        float4 o;
        o.x = v.x * g.x; o.y = v.y * g.y; o.z = v.z * g.z; o.w = v.w * g.w;
        out[i] = o;
    }
}

// ---------------------------------------------------------------------------
extern "C" void kernel_launch(void* const* d_in, const int* in_sizes, int n_in,
                              void* d_out, int out_size) {
    const float* feats = (const float*)d_in[0];
    const int*   idx   = (const int*)  d_in[1];
    const float* W1    = (const float*)d_in[2];
    const float* b1    = (const float*)d_in[3];
    const float* W2    = (const float*)d_in[4];
    const float* b2    = (const float*)d_in[5];

    const int N = in_sizes[1];               // number of points
    const long total4 = (long)N * C4;

    se_zero_kernel<<<(NUM_SEG * C + 255) / 256, 256>>>();

    se_reduce_kernel<<<RED_BLOCKS, 256>>>((const float4*)feats, idx, N);

    se_mlp_kernel<<<NUM_SEG, 256>>>(idx, N, W1, b1, W2, b2);

    se_scale_kernel<<<2368, 256>>>((const float4*)feats, idx,
                                   (float4*)d_out, total4);
}